// round 4
// baseline (speedup 1.0000x reference)
#include <cuda_runtime.h>
#include <math.h>

#define T 32
#define N 512
#define E 64
#define F 64
#define HD 64
#define SLOPE 0.2f

// ---------------- device scratch ----------------
__device__ float g_h[T * N * HD];       // 4 MB
__device__ float g_shyp[T * N];
__device__ float g_sind[T * N];
__device__ float g_emax[T * E];
__device__ float g_einv[T * E];
__device__ float g_ind[T * N * HD];     // 4 MB
__device__ int   g_adj_cnt[N];
__device__ int   g_adj_nbr[N * N];
__device__ int   g_ne_cnt[N];
__device__ int   g_ne_off[N];
__device__ int   g_ne_lst[N * E];
__device__ int   g_en_cnt[E];
__device__ int   g_en_lst[E * N];
__device__ int   g_wl_n[N * E];
__device__ int   g_wl_e[N * E];
__device__ int   g_nnz;
__device__ int   g_Mhyp;
__device__ int   g_Mtot;
__device__ float g_zall[T * N * E + T * N];

__device__ __forceinline__ float elu1(float v) { return v > 0.f ? v : expm1f(v); }

// ---------------- fused pre: CSR(adj), CSR(edge->node), CSR(node->edge)+scan+worklist ----------------
// grid: 32 blocks adj (16 rows each) + 4 blocks en (16 edges each) + 1 block ne/scan. 512 thr.
__global__ void __launch_bounds__(512) k_pre(const int* __restrict__ adj,
                                             const int* __restrict__ Hm) {
    int b = blockIdx.x;
    int lane = threadIdx.x & 31;
    int wl = threadIdx.x >> 5;                // warp in block (0..15)
    if (b < 32) {                              // adjacency rows
        int i = b * 16 + wl;
        int cnt = 0;
        #pragma unroll
        for (int c = 0; c < N / 32; c++) {
            int j = c * 32 + lane;
            bool m = adj[i * N + j] != 0;
            unsigned bl = __ballot_sync(0xffffffffu, m);
            if (m) g_adj_nbr[i * N + cnt + __popc(bl & ((1u << lane) - 1u))] = j;
            cnt += __popc(bl);
        }
        if (lane == 0) g_adj_cnt[i] = cnt;
    } else if (b < 36) {                       // edge -> member nodes
        int e = (b - 32) * 16 + wl;
        int cnt = 0;
        #pragma unroll
        for (int c = 0; c < N / 32; c++) {
            int n = c * 32 + lane;
            bool m = Hm[n * E + e] != 0;
            unsigned bl = __ballot_sync(0xffffffffu, m);
            if (m) g_en_lst[e * N + cnt + __popc(bl & ((1u << lane) - 1u))] = n;
            cnt += __popc(bl);
        }
        if (lane == 0) g_en_cnt[e] = cnt;
    } else {                                   // node->edge CSR + scan + worklist
        __shared__ int buf[N];
        int n = threadIdx.x;                   // 512 threads = N
        int el[16];                            // local member-edge list (deg <= E, cap 16 safe? no)
        int cnt = 0;
        // build list: write directly to global (deg can exceed 16)
        #pragma unroll
        for (int e = 0; e < E; e++) {
            if (Hm[n * E + e] != 0) {
                g_ne_lst[n * E + cnt] = e;
                if (cnt < 16) el[cnt] = e;
                cnt++;
            }
        }
        g_ne_cnt[n] = cnt;
        buf[n] = cnt;
        __syncthreads();
        #pragma unroll
        for (int o = 1; o < N; o <<= 1) {
            int add = (n >= o) ? buf[n - o] : 0;
            __syncthreads();
            buf[n] += add;
            __syncthreads();
        }
        int off = buf[n] - cnt;
        g_ne_off[n] = off;
        if (n == N - 1) {
            int nnz = buf[N - 1];
            g_nnz = nnz;
            g_Mhyp = T * nnz;
            g_Mtot = T * nnz + T * N;
        }
        for (int j = 0; j < cnt; j++) {
            int e = (j < 16) ? el[j] : g_ne_lst[n * E + j];
            g_wl_n[off + j] = n;
            g_wl_e[off + j] = e;
        }
    }
}

// ---------------- h = x@W (smem-tiled GEMM) + fused s_hyp / s_ind ----------------
__global__ void __launch_bounds__(256) k_h(const float* __restrict__ x,
                                           const float* __restrict__ W,
                                           const float* __restrict__ ah,
                                           const float* __restrict__ ai) {
    __shared__ float xs[32][65];
    __shared__ float ws[64][65];
    int tid = threadIdx.x;
    int r0 = blockIdx.x * 32;

    for (int i = tid; i < 32 * 64; i += 256) {
        int r = i >> 6, c = i & 63;
        xs[r][c] = x[(r0 + r) * F + c];
    }
    for (int i = tid; i < 64 * 64; i += 256) {
        int r = i >> 6, c = i & 63;
        ws[r][c] = W[i];
    }
    __syncthreads();

    int ty = tid >> 4, tx = tid & 15;
    float acc[2][4] = {{0.f,0.f,0.f,0.f},{0.f,0.f,0.f,0.f}};
    #pragma unroll 8
    for (int k = 0; k < 64; k++) {
        float xr0 = xs[ty * 2 + 0][k];
        float xr1 = xs[ty * 2 + 1][k];
        float wv[4];
        #pragma unroll
        for (int j = 0; j < 4; j++) wv[j] = ws[k][tx * 4 + j];
        #pragma unroll
        for (int j = 0; j < 4; j++) {
            acc[0][j] = fmaf(xr0, wv[j], acc[0][j]);
            acc[1][j] = fmaf(xr1, wv[j], acc[1][j]);
        }
    }
    __syncthreads();
    #pragma unroll
    for (int i = 0; i < 2; i++) {
        int r = ty * 2 + i;
        #pragma unroll
        for (int j = 0; j < 4; j++) xs[r][tx * 4 + j] = acc[i][j];
        float4 v = make_float4(acc[i][0], acc[i][1], acc[i][2], acc[i][3]);
        *(float4*)&g_h[(r0 + r) * HD + tx * 4] = v;
    }
    __syncthreads();

    int row = tid >> 3, oct = tid & 7;
    float sh = 0.f, si = 0.f;
    #pragma unroll
    for (int k = 0; k < 8; k++) {
        float v = xs[row][oct * 8 + k];
        sh = fmaf(v, __ldg(&ah[oct * 8 + k]), sh);
        si = fmaf(v, __ldg(&ai[oct * 8 + k]), si);
    }
    #pragma unroll
    for (int o = 4; o > 0; o >>= 1) {
        sh += __shfl_xor_sync(0xffffffffu, sh, o);
        si += __shfl_xor_sync(0xffffffffu, si, o);
    }
    if (oct == 0) {
        g_shyp[r0 + row] = sh >= 0.f ? sh : SLOPE * sh;
        g_sind[r0 + row] = si >= 0.f ? si : SLOPE * si;
    }
}

// ---------------- fused: industry (warp-per-row, float2 lanes) + hyperedge stats ----------------
__global__ void __launch_bounds__(256) k_mid() {
    int b = blockIdx.x;
    int tid = threadIdx.x;
    int lane = tid & 31;
    int wrp = tid >> 5;
    if (b < 2048) {
        __shared__ float smw[8][512];
        int row = b * 8 + wrp;                 // t*N + i
        int t = row >> 9;
        int i = row & (N - 1);
        int deg = g_adj_cnt[i];
        const int* nbr = g_adj_nbr + i * N;
        const float* si = g_sind + t * N;

        float m = -3.0e38f;
        for (int k = lane; k < deg; k += 32) m = fmaxf(m, si[nbr[k]]);
        #pragma unroll
        for (int o = 16; o > 0; o >>= 1) m = fmaxf(m, __shfl_xor_sync(0xffffffffu, m, o));
        float s = 0.f;
        for (int k = lane; k < deg; k += 32) {
            float w = expf(si[nbr[k]] - m);
            smw[wrp][k] = w;
            s += w;
        }
        #pragma unroll
        for (int o = 16; o > 0; o >>= 1) s += __shfl_xor_sync(0xffffffffu, s, o);
        float inv = 1.f / s;
        __syncwarp();

        const float* hb = g_h + t * N * HD;
        float2 a0 = {0.f,0.f}, a1 = {0.f,0.f}, a2 = {0.f,0.f}, a3 = {0.f,0.f};
        int k = 0;
        for (; k + 4 <= deg; k += 4) {
            float w0 = smw[wrp][k],     w1 = smw[wrp][k + 1];
            float w2 = smw[wrp][k + 2], w3 = smw[wrp][k + 3];
            float2 h0 = *(const float2*)&hb[nbr[k]     * HD + lane * 2];
            float2 h1 = *(const float2*)&hb[nbr[k + 1] * HD + lane * 2];
            float2 h2 = *(const float2*)&hb[nbr[k + 2] * HD + lane * 2];
            float2 h3 = *(const float2*)&hb[nbr[k + 3] * HD + lane * 2];
            a0.x = fmaf(w0, h0.x, a0.x); a0.y = fmaf(w0, h0.y, a0.y);
            a1.x = fmaf(w1, h1.x, a1.x); a1.y = fmaf(w1, h1.y, a1.y);
            a2.x = fmaf(w2, h2.x, a2.x); a2.y = fmaf(w2, h2.y, a2.y);
            a3.x = fmaf(w3, h3.x, a3.x); a3.y = fmaf(w3, h3.y, a3.y);
        }
        for (; k < deg; k++) {
            float w0 = smw[wrp][k];
            float2 h0 = *(const float2*)&hb[nbr[k] * HD + lane * 2];
            a0.x = fmaf(w0, h0.x, a0.x); a0.y = fmaf(w0, h0.y, a0.y);
        }
        float2 r;
        r.x = ((a0.x + a1.x) + (a2.x + a3.x)) * inv;
        r.y = ((a0.y + a1.y) + (a2.y + a3.y)) * inv;
        *(float2*)&g_ind[row * HD + lane * 2] = r;
    } else {
        int w = (b - 2048) * 8 + wrp;          // (t,e) 0..2047
        int t = w / E, e = w % E;
        int cnt = g_en_cnt[e];
        const int* lst = g_en_lst + e * N;
        const float* sh = g_shyp + t * N;
        float m = -3.0e38f;
        for (int i = lane; i < cnt; i += 32) m = fmaxf(m, sh[lst[i]]);
        #pragma unroll
        for (int o = 16; o > 0; o >>= 1) m = fmaxf(m, __shfl_xor_sync(0xffffffffu, m, o));
        float s = 0.f;
        for (int i = lane; i < cnt; i += 32) s += expf(sh[lst[i]] - m);
        #pragma unroll
        for (int o = 16; o > 0; o >>= 1) s += __shfl_xor_sync(0xffffffffu, s, o);
        if (lane == 0) { g_emax[w] = m; g_einv[w] = 1.f / s; }
    }
}

// ---------------- phase A: 128-row tiles, 128 threads, transposed feats, shuffle-z ----------------
__global__ void __launch_bounds__(128) k_scoreA(const float* __restrict__ Wc1g,
                                                const float* __restrict__ bc1g,
                                                const float* __restrict__ wc2g,
                                                const float* __restrict__ bc2g) {
    __shared__ float Ws[HD * HD];              // 16 KB
    __shared__ float fsT[HD * 128];            // 32 KB, [k][row]
    int tid = threadIdx.x;
    int tx = tid & 7;                          // col group (8 cols)
    int ty = tid >> 3;                         // row group (8 rows), 0..15

    for (int i = tid; i < HD * HD; i += 128) Ws[i] = Wc1g[i];
    float bc1r[8], wc2r[8];
    #pragma unroll
    for (int j = 0; j < 8; j++) {
        bc1r[j] = __ldg(&bc1g[tx * 8 + j]);
        wc2r[j] = __ldg(&wc2g[tx * 8 + j]);
    }
    float bc2 = __ldg(&bc2g[0]);
    int Mtot = g_Mtot, Mhyp = g_Mhyp, nnz = g_nnz;
    int ntiles = (Mtot + 127) >> 7;

    for (int tile = blockIdx.x; tile < ntiles; tile += gridDim.x) {
        __syncthreads();
        int row = tile * 128 + tid;
        if (row < Mhyp) {
            int t = row / nnz;
            int idx = row - t * nnz;
            int n = g_wl_n[idx], e = g_wl_e[idx];
            float a = expf(g_shyp[t * N + n] - g_emax[t * E + e]) * g_einv[t * E + e];
            const float4* hp = (const float4*)&g_h[(t * N + n) * HD];
            #pragma unroll
            for (int q = 0; q < 16; q++) {
                float4 v = hp[q];
                fsT[(q * 4 + 0) * 128 + tid] = elu1(a * v.x);
                fsT[(q * 4 + 1) * 128 + tid] = elu1(a * v.y);
                fsT[(q * 4 + 2) * 128 + tid] = elu1(a * v.z);
                fsT[(q * 4 + 3) * 128 + tid] = elu1(a * v.w);
            }
        } else if (row < Mtot) {
            const float4* ip = (const float4*)&g_ind[(row - Mhyp) * HD];
            #pragma unroll
            for (int q = 0; q < 16; q++) {
                float4 v = ip[q];
                fsT[(q * 4 + 0) * 128 + tid] = v.x;
                fsT[(q * 4 + 1) * 128 + tid] = v.y;
                fsT[(q * 4 + 2) * 128 + tid] = v.z;
                fsT[(q * 4 + 3) * 128 + tid] = v.w;
            }
        } else {
            #pragma unroll
            for (int q = 0; q < 64; q++) fsT[q * 128 + tid] = 0.f;
        }
        __syncthreads();

        float acc[8][8];
        #pragma unroll
        for (int i = 0; i < 8; i++)
            #pragma unroll
            for (int j = 0; j < 8; j++) acc[i][j] = 0.f;

        #pragma unroll 8
        for (int k = 0; k < HD; k++) {
            float4 f0 = *(const float4*)&fsT[k * 128 + ty * 8];
            float4 f1 = *(const float4*)&fsT[k * 128 + ty * 8 + 4];
            float4 w0 = *(const float4*)&Ws[k * HD + tx * 8];
            float4 w1 = *(const float4*)&Ws[k * HD + tx * 8 + 4];
            float fv[8] = {f0.x, f0.y, f0.z, f0.w, f1.x, f1.y, f1.z, f1.w};
            float wv[8] = {w0.x, w0.y, w0.z, w0.w, w1.x, w1.y, w1.z, w1.w};
            #pragma unroll
            for (int i = 0; i < 8; i++)
                #pragma unroll
                for (int j = 0; j < 8; j++)
                    acc[i][j] = fmaf(fv[i], wv[j], acc[i][j]);
        }

        // epilogue: z per row, reduce across 8-lane col groups
        float zr[8];
        #pragma unroll
        for (int i = 0; i < 8; i++) {
            float p = 0.f;
            #pragma unroll
            for (int j = 0; j < 8; j++)
                p = fmaf(fmaxf(acc[i][j] + bc1r[j], 0.f), wc2r[j], p);
            p += __shfl_down_sync(0xffffffffu, p, 4, 8);
            p += __shfl_down_sync(0xffffffffu, p, 2, 8);
            p += __shfl_down_sync(0xffffffffu, p, 1, 8);
            zr[i] = p + bc2;
        }
        if (tx == 0) {
            int rb = tile * 128 + ty * 8;
            #pragma unroll
            for (int i = 0; i < 8; i++)
                if (rb + i < Mtot) g_zall[rb + i] = zr[i];
        }
    }
}

// ---------------- phase B: y8 build + score + final combine ----------------
__global__ void __launch_bounds__(64) k_scoreBfin(float* __restrict__ out,
                                                  const float* __restrict__ Wc1g,
                                                  const float* __restrict__ bc1g,
                                                  const float* __restrict__ wc2g,
                                                  const float* __restrict__ bc2g) {
    __shared__ float Ws[HD * HD];
    __shared__ float fs[64 * 65];
    __shared__ float zp[64 * 9];
    int tid = threadIdx.x;
    int ty = tid >> 3, tx = tid & 7;

    for (int i = tid; i < HD * HD; i += 64) Ws[i] = Wc1g[i];
    float bc1r[8], wc2r[8];
    #pragma unroll
    for (int j = 0; j < 8; j++) {
        bc1r[j] = __ldg(&bc1g[tx * 8 + j]);
        wc2r[j] = __ldg(&wc2g[tx * 8 + j]);
    }
    float bc2 = __ldg(&bc2g[0]);
    int Mhyp = g_Mhyp, nnz = g_nnz;

    int row = blockIdx.x * 64 + tid;
    int t = row >> 9, n = row & (N - 1);
    int deg = g_ne_cnt[n];
    int off = g_ne_off[n];

    {
        float hreg[64];
        const float4* hp = (const float4*)&g_h[row * HD];
        #pragma unroll
        for (int q = 0; q < 16; q++) {
            float4 v = hp[q];
            hreg[q * 4 + 0] = v.x; hreg[q * 4 + 1] = v.y;
            hreg[q * 4 + 2] = v.z; hreg[q * 4 + 3] = v.w;
        }
        float shn = g_shyp[row];
        const float* zb = g_zall + t * nnz + off;
        const int* el = g_ne_lst + n * E;
        float M = -3.0e38f;
        for (int j = 0; j < deg; j++) M = fmaxf(M, zb[j]);
        float y8v[64];
        #pragma unroll
        for (int q = 0; q < 64; q++) y8v[q] = 0.f;
        float S = 0.f;
        for (int j = 0; j < deg; j++) {
            float w = expf(zb[j] - M);
            S += w;
            int e = el[j];
            float a = expf(shn - g_emax[t * E + e]) * g_einv[t * E + e];
            #pragma unroll
            for (int q = 0; q < 64; q++)
                y8v[q] = fmaf(w, elu1(a * hreg[q]), y8v[q]);
        }
        float inv = 1.f / S;
        #pragma unroll
        for (int q = 0; q < 64; q++) fs[tid * 65 + q] = y8v[q] * inv;
    }
    __syncthreads();

    float acc[8][8];
    #pragma unroll
    for (int i = 0; i < 8; i++)
        #pragma unroll
        for (int j = 0; j < 8; j++) acc[i][j] = 0.f;
    #pragma unroll 8
    for (int k = 0; k < HD; k++) {
        float fv[8];
        #pragma unroll
        for (int i = 0; i < 8; i++) fv[i] = fs[(ty * 8 + i) * 65 + k];
        float4 w0 = *(const float4*)&Ws[k * HD + tx * 8];
        float4 w1 = *(const float4*)&Ws[k * HD + tx * 8 + 4];
        float wv[8] = {w0.x, w0.y, w0.z, w0.w, w1.x, w1.y, w1.z, w1.w};
        #pragma unroll
        for (int i = 0; i < 8; i++)
            #pragma unroll
            for (int j = 0; j < 8; j++)
                acc[i][j] = fmaf(fv[i], wv[j], acc[i][j]);
    }

    #pragma unroll
    for (int i = 0; i < 8; i++) {
        float p = 0.f;
        #pragma unroll
        for (int j = 0; j < 8; j++)
            p = fmaf(fmaxf(acc[i][j] + bc1r[j], 0.f), wc2r[j], p);
        zp[(ty * 8 + i) * 9 + tx] = p;
    }
    __syncthreads();

    float z2 = bc2;
    #pragma unroll
    for (int q = 0; q < 8; q++) z2 += zp[tid * 9 + q];
    float z1 = g_zall[Mhyp + row];
    float m2 = fmaxf(z1, z2);
    float w1 = expf(z1 - m2), w2 = expf(z2 - m2);
    float inv = 1.f / (w1 + w2);
    const float4* ip = (const float4*)&g_ind[row * HD];
    float4* op = (float4*)&out[row * HD];
    #pragma unroll
    for (int q = 0; q < 16; q++) {
        float4 iv = ip[q];
        float4 r;
        r.x = (w1 * iv.x + w2 * fs[tid * 65 + q * 4 + 0]) * inv;
        r.y = (w1 * iv.y + w2 * fs[tid * 65 + q * 4 + 1]) * inv;
        r.z = (w1 * iv.z + w2 * fs[tid * 65 + q * 4 + 2]) * inv;
        r.w = (w1 * iv.w + w2 * fs[tid * 65 + q * 4 + 3]) * inv;
        op[q] = r;
    }
}

// ---------------- launch ----------------
extern "C" void kernel_launch(void* const* d_in, const int* in_sizes, int n_in,
                              void* d_out, int out_size) {
    int off = (n_in >= 11) ? 1 : 0;
    const float* x   = (const float*)d_in[0];
    const int*   Hm  = (const int*)d_in[1];
    const int*   adj = (const int*)d_in[2];
    const float* W   = (const float*)d_in[3 + off];
    const float* ah  = (const float*)d_in[4 + off];
    const float* ai  = (const float*)d_in[5 + off];
    const float* Wc1 = (const float*)d_in[6 + off];
    const float* bc1 = (const float*)d_in[7 + off];
    const float* wc2 = (const float*)d_in[8 + off];
    const float* bc2 = (const float*)d_in[9 + off];
    float* outp = (float*)d_out;

    k_pre<<<37, 512>>>(adj, Hm);
    k_h<<<T * N / 32, 256>>>(x, W, ah, ai);
    k_mid<<<2048 + 256, 256>>>();
    k_scoreA<<<592, 128>>>(Wc1, bc1, wc2, bc2);
    k_scoreBfin<<<T * N / 64, 64>>>(outp, Wc1, bc1, wc2, bc2);
}

// round 5
// speedup vs baseline: 1.2597x; 1.2597x over previous
#include <cuda_runtime.h>
#include <math.h>

#define T 32
#define N 512
#define E 64
#define F 64
#define HD 64
#define SLOPE 0.2f

// ---------------- device scratch ----------------
__device__ float g_h[T * N * HD];       // 4 MB
__device__ float g_shyp[T * N];
__device__ float g_sind[T * N];
__device__ float g_emax[T * E];
__device__ float g_einv[T * E];
__device__ float g_ind[T * N * HD];     // 4 MB
__device__ int   g_adj_cnt[N];
__device__ int   g_adj_nbr[N * N];
__device__ int   g_ne_cnt[N];
__device__ int   g_ne_off[N];
__device__ int   g_ne_lst[N * E];
__device__ int   g_en_cnt[E];
__device__ int   g_en_lst[E * N];
__device__ int   g_wl_n[N * E];
__device__ int   g_wl_e[N * E];
__device__ int   g_nnz;
__device__ int   g_Mhyp;
__device__ int   g_Mtot;
__device__ float g_zall[T * N * E + T * N];

__device__ __forceinline__ float elu1(float v) { return v > 0.f ? v : expm1f(v); }

// ---------------- fused pre: CSR(adj), CSR(edge->node), CSR(node->edge)+scan+worklist ----------------
__global__ void __launch_bounds__(512) k_pre(const int* __restrict__ adj,
                                             const int* __restrict__ Hm) {
    int b = blockIdx.x;
    int lane = threadIdx.x & 31;
    int wl = threadIdx.x >> 5;
    if (b < 32) {                              // adjacency rows
        int i = b * 16 + wl;
        int cnt = 0;
        #pragma unroll
        for (int c = 0; c < N / 32; c++) {
            int j = c * 32 + lane;
            bool m = adj[i * N + j] != 0;
            unsigned bl = __ballot_sync(0xffffffffu, m);
            if (m) g_adj_nbr[i * N + cnt + __popc(bl & ((1u << lane) - 1u))] = j;
            cnt += __popc(bl);
        }
        if (lane == 0) g_adj_cnt[i] = cnt;
    } else if (b < 36) {                       // edge -> member nodes
        int e = (b - 32) * 16 + wl;
        int cnt = 0;
        #pragma unroll
        for (int c = 0; c < N / 32; c++) {
            int n = c * 32 + lane;
            bool m = Hm[n * E + e] != 0;
            unsigned bl = __ballot_sync(0xffffffffu, m);
            if (m) g_en_lst[e * N + cnt + __popc(bl & ((1u << lane) - 1u))] = n;
            cnt += __popc(bl);
        }
        if (lane == 0) g_en_cnt[e] = cnt;
    } else {                                   // node->edge CSR + scan + worklist
        __shared__ int buf[N];
        int n = threadIdx.x;
        int el[16];
        int cnt = 0;
        #pragma unroll
        for (int e = 0; e < E; e++) {
            if (Hm[n * E + e] != 0) {
                g_ne_lst[n * E + cnt] = e;
                if (cnt < 16) el[cnt] = e;
                cnt++;
            }
        }
        g_ne_cnt[n] = cnt;
        buf[n] = cnt;
        __syncthreads();
        #pragma unroll
        for (int o = 1; o < N; o <<= 1) {
            int add = (n >= o) ? buf[n - o] : 0;
            __syncthreads();
            buf[n] += add;
            __syncthreads();
        }
        int off = buf[n] - cnt;
        g_ne_off[n] = off;
        if (n == N - 1) {
            int nnz = buf[N - 1];
            g_nnz = nnz;
            g_Mhyp = T * nnz;
            g_Mtot = T * nnz + T * N;
        }
        for (int j = 0; j < cnt; j++) {
            int e = (j < 16) ? el[j] : g_ne_lst[n * E + j];
            g_wl_n[off + j] = n;
            g_wl_e[off + j] = e;
        }
    }
}

// ---------------- h = x@W (smem-tiled GEMM) + fused s_hyp / s_ind ----------------
__global__ void __launch_bounds__(256) k_h(const float* __restrict__ x,
                                           const float* __restrict__ W,
                                           const float* __restrict__ ah,
                                           const float* __restrict__ ai) {
    __shared__ float xs[32][65];
    __shared__ float ws[64][65];
    int tid = threadIdx.x;
    int r0 = blockIdx.x * 32;

    for (int i = tid; i < 32 * 64; i += 256) {
        int r = i >> 6, c = i & 63;
        xs[r][c] = x[(r0 + r) * F + c];
    }
    for (int i = tid; i < 64 * 64; i += 256) {
        int r = i >> 6, c = i & 63;
        ws[r][c] = W[i];
    }
    __syncthreads();

    int ty = tid >> 4, tx = tid & 15;
    float acc[2][4] = {{0.f,0.f,0.f,0.f},{0.f,0.f,0.f,0.f}};
    #pragma unroll 8
    for (int k = 0; k < 64; k++) {
        float xr0 = xs[ty * 2 + 0][k];
        float xr1 = xs[ty * 2 + 1][k];
        float wv[4];
        #pragma unroll
        for (int j = 0; j < 4; j++) wv[j] = ws[k][tx * 4 + j];
        #pragma unroll
        for (int j = 0; j < 4; j++) {
            acc[0][j] = fmaf(xr0, wv[j], acc[0][j]);
            acc[1][j] = fmaf(xr1, wv[j], acc[1][j]);
        }
    }
    __syncthreads();
    #pragma unroll
    for (int i = 0; i < 2; i++) {
        int r = ty * 2 + i;
        #pragma unroll
        for (int j = 0; j < 4; j++) xs[r][tx * 4 + j] = acc[i][j];
        float4 v = make_float4(acc[i][0], acc[i][1], acc[i][2], acc[i][3]);
        *(float4*)&g_h[(r0 + r) * HD + tx * 4] = v;
    }
    __syncthreads();

    int row = tid >> 3, oct = tid & 7;
    float sh = 0.f, si = 0.f;
    #pragma unroll
    for (int k = 0; k < 8; k++) {
        float v = xs[row][oct * 8 + k];
        sh = fmaf(v, __ldg(&ah[oct * 8 + k]), sh);
        si = fmaf(v, __ldg(&ai[oct * 8 + k]), si);
    }
    #pragma unroll
    for (int o = 4; o > 0; o >>= 1) {
        sh += __shfl_xor_sync(0xffffffffu, sh, o);
        si += __shfl_xor_sync(0xffffffffu, si, o);
    }
    if (oct == 0) {
        g_shyp[r0 + row] = sh >= 0.f ? sh : SLOPE * sh;
        g_sind[r0 + row] = si >= 0.f ? si : SLOPE * si;
    }
}

// ---------------- fused: industry (warp-per-row, float2 lanes) + hyperedge stats ----------------
__global__ void __launch_bounds__(256) k_mid() {
    int b = blockIdx.x;
    int tid = threadIdx.x;
    int lane = tid & 31;
    int wrp = tid >> 5;
    if (b < 2048) {
        __shared__ float smw[8][512];
        int row = b * 8 + wrp;
        int t = row >> 9;
        int i = row & (N - 1);
        int deg = g_adj_cnt[i];
        const int* nbr = g_adj_nbr + i * N;
        const float* si = g_sind + t * N;

        float m = -3.0e38f;
        for (int k = lane; k < deg; k += 32) m = fmaxf(m, si[nbr[k]]);
        #pragma unroll
        for (int o = 16; o > 0; o >>= 1) m = fmaxf(m, __shfl_xor_sync(0xffffffffu, m, o));
        float s = 0.f;
        for (int k = lane; k < deg; k += 32) {
            float w = expf(si[nbr[k]] - m);
            smw[wrp][k] = w;
            s += w;
        }
        #pragma unroll
        for (int o = 16; o > 0; o >>= 1) s += __shfl_xor_sync(0xffffffffu, s, o);
        float inv = 1.f / s;
        __syncwarp();

        const float* hb = g_h + t * N * HD;
        float2 a0 = {0.f,0.f}, a1 = {0.f,0.f}, a2 = {0.f,0.f}, a3 = {0.f,0.f};
        int k = 0;
        for (; k + 4 <= deg; k += 4) {
            float w0 = smw[wrp][k],     w1 = smw[wrp][k + 1];
            float w2 = smw[wrp][k + 2], w3 = smw[wrp][k + 3];
            float2 h0 = *(const float2*)&hb[nbr[k]     * HD + lane * 2];
            float2 h1 = *(const float2*)&hb[nbr[k + 1] * HD + lane * 2];
            float2 h2 = *(const float2*)&hb[nbr[k + 2] * HD + lane * 2];
            float2 h3 = *(const float2*)&hb[nbr[k + 3] * HD + lane * 2];
            a0.x = fmaf(w0, h0.x, a0.x); a0.y = fmaf(w0, h0.y, a0.y);
            a1.x = fmaf(w1, h1.x, a1.x); a1.y = fmaf(w1, h1.y, a1.y);
            a2.x = fmaf(w2, h2.x, a2.x); a2.y = fmaf(w2, h2.y, a2.y);
            a3.x = fmaf(w3, h3.x, a3.x); a3.y = fmaf(w3, h3.y, a3.y);
        }
        for (; k < deg; k++) {
            float w0 = smw[wrp][k];
            float2 h0 = *(const float2*)&hb[nbr[k] * HD + lane * 2];
            a0.x = fmaf(w0, h0.x, a0.x); a0.y = fmaf(w0, h0.y, a0.y);
        }
        float2 r;
        r.x = ((a0.x + a1.x) + (a2.x + a3.x)) * inv;
        r.y = ((a0.y + a1.y) + (a2.y + a3.y)) * inv;
        *(float2*)&g_ind[row * HD + lane * 2] = r;
    } else {
        int w = (b - 2048) * 8 + wrp;
        int t = w / E, e = w % E;
        int cnt = g_en_cnt[e];
        const int* lst = g_en_lst + e * N;
        const float* sh = g_shyp + t * N;
        float m = -3.0e38f;
        for (int i = lane; i < cnt; i += 32) m = fmaxf(m, sh[lst[i]]);
        #pragma unroll
        for (int o = 16; o > 0; o >>= 1) m = fmaxf(m, __shfl_xor_sync(0xffffffffu, m, o));
        float s = 0.f;
        for (int i = lane; i < cnt; i += 32) s += expf(sh[lst[i]] - m);
        #pragma unroll
        for (int o = 16; o > 0; o >>= 1) s += __shfl_xor_sync(0xffffffffu, s, o);
        if (lane == 0) { g_emax[w] = m; g_einv[w] = 1.f / s; }
    }
}

// ---------------- GEMM macro: 64 rows x 64 cols, 256 threads, 4x4 tiles ----------------
// inputs: fsT [k][row] (64x64), Ws [k][col] (64x64). Produces zrow via width-16 shuffle.
#define SCORE_GEMM_Z(ZSTORE)                                                     \
    {                                                                            \
        float acc[4][4];                                                         \
        _Pragma("unroll")                                                        \
        for (int i = 0; i < 4; i++)                                              \
            _Pragma("unroll")                                                    \
            for (int j = 0; j < 4; j++) acc[i][j] = 0.f;                         \
        _Pragma("unroll 16")                                                     \
        for (int k = 0; k < HD; k++) {                                           \
            float4 f = *(const float4*)&fsT[k * 64 + ty * 4];                    \
            float4 w = *(const float4*)&Ws[k * HD + tx * 4];                     \
            float fv[4] = {f.x, f.y, f.z, f.w};                                  \
            float wv[4] = {w.x, w.y, w.z, w.w};                                  \
            _Pragma("unroll")                                                    \
            for (int i = 0; i < 4; i++)                                          \
                _Pragma("unroll")                                                \
                for (int j = 0; j < 4; j++)                                      \
                    acc[i][j] = fmaf(fv[i], wv[j], acc[i][j]);                   \
        }                                                                        \
        _Pragma("unroll")                                                        \
        for (int i = 0; i < 4; i++) {                                            \
            float p = 0.f;                                                       \
            _Pragma("unroll")                                                    \
            for (int j = 0; j < 4; j++)                                          \
                p = fmaf(fmaxf(acc[i][j] + bc1r[j], 0.f), wc2r[j], p);           \
            p += __shfl_down_sync(0xffffffffu, p, 8, 16);                        \
            p += __shfl_down_sync(0xffffffffu, p, 4, 16);                        \
            p += __shfl_down_sync(0xffffffffu, p, 2, 16);                        \
            p += __shfl_down_sync(0xffffffffu, p, 1, 16);                        \
            p += bc2;                                                            \
            if (tx == 0) { ZSTORE; }                                             \
        }                                                                        \
    }

// ---------------- phase A: scores for hyperedge instances + industry rows ----------------
__global__ void __launch_bounds__(256) k_scoreA(const float* __restrict__ Wc1g,
                                                const float* __restrict__ bc1g,
                                                const float* __restrict__ wc2g,
                                                const float* __restrict__ bc2g) {
    __shared__ float Ws[HD * HD];              // 16 KB
    __shared__ float fsT[HD * 64];             // 16 KB, [k][row]
    int tid = threadIdx.x;
    int tx = tid & 15, ty = tid >> 4;
    int r = tid & 63, dgrp = tid >> 6;         // fill mapping

    for (int i = tid; i < HD * HD; i += 256) Ws[i] = Wc1g[i];
    float bc1r[4], wc2r[4];
    #pragma unroll
    for (int j = 0; j < 4; j++) {
        bc1r[j] = __ldg(&bc1g[tx * 4 + j]);
        wc2r[j] = __ldg(&wc2g[tx * 4 + j]);
    }
    float bc2 = __ldg(&bc2g[0]);
    int Mtot = g_Mtot, Mhyp = g_Mhyp, nnz = g_nnz;
    int ntiles = (Mtot + 63) >> 6;

    for (int tile = blockIdx.x; tile < ntiles; tile += gridDim.x) {
        __syncthreads();
        int row = tile * 64 + r;
        if (row < Mhyp) {
            int t = row / nnz;
            int idx = row - t * nnz;
            int n = g_wl_n[idx], e = g_wl_e[idx];
            float a = expf(g_shyp[t * N + n] - g_emax[t * E + e]) * g_einv[t * E + e];
            const float4* hp = (const float4*)&g_h[(t * N + n) * HD + dgrp * 16];
            #pragma unroll
            for (int q = 0; q < 4; q++) {
                float4 v = hp[q];
                fsT[(dgrp * 16 + q * 4 + 0) * 64 + r] = elu1(a * v.x);
                fsT[(dgrp * 16 + q * 4 + 1) * 64 + r] = elu1(a * v.y);
                fsT[(dgrp * 16 + q * 4 + 2) * 64 + r] = elu1(a * v.z);
                fsT[(dgrp * 16 + q * 4 + 3) * 64 + r] = elu1(a * v.w);
            }
        } else if (row < Mtot) {
            const float4* ip = (const float4*)&g_ind[(row - Mhyp) * HD + dgrp * 16];
            #pragma unroll
            for (int q = 0; q < 4; q++) {
                float4 v = ip[q];
                fsT[(dgrp * 16 + q * 4 + 0) * 64 + r] = v.x;
                fsT[(dgrp * 16 + q * 4 + 1) * 64 + r] = v.y;
                fsT[(dgrp * 16 + q * 4 + 2) * 64 + r] = v.z;
                fsT[(dgrp * 16 + q * 4 + 3) * 64 + r] = v.w;
            }
        } else {
            #pragma unroll
            for (int q = 0; q < 16; q++) fsT[(dgrp * 16 + q) * 64 + r] = 0.f;
        }
        __syncthreads();

        int rb = tile * 64 + ty * 4;
        SCORE_GEMM_Z(if (rb + i < Mtot) g_zall[rb + i] = p);
    }
}

// ---------------- phase B: y8 build (4 thr/row) + score + final combine ----------------
__global__ void __launch_bounds__(256) k_scoreBfin(float* __restrict__ out,
                                                   const float* __restrict__ Wc1g,
                                                   const float* __restrict__ bc1g,
                                                   const float* __restrict__ wc2g,
                                                   const float* __restrict__ bc2g) {
    __shared__ float Ws[HD * HD];
    __shared__ float fsT[HD * 64];
    __shared__ float zs[64];
    int tid = threadIdx.x;
    int tx = tid & 15, ty = tid >> 4;
    int r = tid & 63, dgrp = tid >> 6;

    for (int i = tid; i < HD * HD; i += 256) Ws[i] = Wc1g[i];
    float bc1r[4], wc2r[4];
    #pragma unroll
    for (int j = 0; j < 4; j++) {
        bc1r[j] = __ldg(&bc1g[tx * 4 + j]);
        wc2r[j] = __ldg(&wc2g[tx * 4 + j]);
    }
    float bc2 = __ldg(&bc2g[0]);
    int Mhyp = g_Mhyp, nnz = g_nnz;

    int row = blockIdx.x * 64 + r;             // (t,n)
    int t = row >> 9, n = row & (N - 1);
    int deg = g_ne_cnt[n];
    int off = g_ne_off[n];

    // phase 1: y8 for 16 dims of this row
    {
        float h16[16];
        const float4* hp = (const float4*)&g_h[row * HD + dgrp * 16];
        #pragma unroll
        for (int q = 0; q < 4; q++) {
            float4 v = hp[q];
            h16[q * 4 + 0] = v.x; h16[q * 4 + 1] = v.y;
            h16[q * 4 + 2] = v.z; h16[q * 4 + 3] = v.w;
        }
        float shn = g_shyp[row];
        const float* zb = g_zall + t * nnz + off;
        const int* el = g_ne_lst + n * E;
        float M = -3.0e38f;
        for (int j = 0; j < deg; j++) M = fmaxf(M, zb[j]);
        float y[16];
        #pragma unroll
        for (int q = 0; q < 16; q++) y[q] = 0.f;
        float S = 0.f;
        for (int j = 0; j < deg; j++) {
            float w = expf(zb[j] - M);
            S += w;
            int e = el[j];
            float a = expf(shn - g_emax[t * E + e]) * g_einv[t * E + e];
            #pragma unroll
            for (int q = 0; q < 16; q++)
                y[q] = fmaf(w, elu1(a * h16[q]), y[q]);
        }
        float inv = 1.f / S;
        #pragma unroll
        for (int q = 0; q < 16; q++)
            fsT[(dgrp * 16 + q) * 64 + r] = y[q] * inv;
    }
    __syncthreads();

    // phase 2: GEMM + z
    SCORE_GEMM_Z(zs[ty * 4 + i] = p);
    __syncthreads();

    // phase 3: combine, 4 threads per row, 16 dims each
    float z2 = zs[r];
    float z1 = g_zall[Mhyp + row];
    float m2 = fmaxf(z1, z2);
    float w1 = expf(z1 - m2), w2 = expf(z2 - m2);
    float inv = 1.f / (w1 + w2);
    const float4* ip = (const float4*)&g_ind[row * HD + dgrp * 16];
    float4* op = (float4*)&out[row * HD + dgrp * 16];
    #pragma unroll
    for (int q = 0; q < 4; q++) {
        float4 iv = ip[q];
        float4 rr;
        rr.x = (w1 * iv.x + w2 * fsT[(dgrp * 16 + q * 4 + 0) * 64 + r]) * inv;
        rr.y = (w1 * iv.y + w2 * fsT[(dgrp * 16 + q * 4 + 1) * 64 + r]) * inv;
        rr.z = (w1 * iv.z + w2 * fsT[(dgrp * 16 + q * 4 + 2) * 64 + r]) * inv;
        rr.w = (w1 * iv.w + w2 * fsT[(dgrp * 16 + q * 4 + 3) * 64 + r]) * inv;
        op[q] = rr;
    }
}

// ---------------- launch ----------------
extern "C" void kernel_launch(void* const* d_in, const int* in_sizes, int n_in,
                              void* d_out, int out_size) {
    int off = (n_in >= 11) ? 1 : 0;
    const float* x   = (const float*)d_in[0];
    const int*   Hm  = (const int*)d_in[1];
    const int*   adj = (const int*)d_in[2];
    const float* W   = (const float*)d_in[3 + off];
    const float* ah  = (const float*)d_in[4 + off];
    const float* ai  = (const float*)d_in[5 + off];
    const float* Wc1 = (const float*)d_in[6 + off];
    const float* bc1 = (const float*)d_in[7 + off];
    const float* wc2 = (const float*)d_in[8 + off];
    const float* bc2 = (const float*)d_in[9 + off];
    float* outp = (float*)d_out;

    k_pre<<<37, 512>>>(adj, Hm);
    k_h<<<T * N / 32, 256>>>(x, W, ah, ai);
    k_mid<<<2048 + 256, 256>>>();
    k_scoreA<<<1024, 256>>>(Wc1, bc1, wc2, bc2);
    k_scoreBfin<<<T * N / 64, 256>>>(outp, Wc1, bc1, wc2, bc2);
}